// round 17
// baseline (speedup 1.0000x reference)
#include <cuda_runtime.h>
#include <cuda_bf16.h>
#include <cuda_fp16.h>
#include <cstdint>

namespace {
constexpr int TT = 10;
constexpr int NTILES = 1024;      // 65536 / 64 samples per tile
constexpr int GRID = 148;
constexpr int THREADS = 512;      // 2 groups x 8 warps; each group owns a tile
// shared fp16 B-tiles [256 n][64 k], 128B rows, swizzled
constexpr int U1F = 0, FF = 32768, U2F = 65536;
constexpr int W1T = 98304;        // fp16 [256 n][32 k] (k0-15 data), 64B rows
constexpr int BIAS1 = 114688, BIAS2 = 115712;   // interleaved [u*4 + gate] f32
constexpr int HG0   = 116736;     // per-group h area: + g*32768
//   h1: HG + buf*8192   (bufs 0,1) ; h2: HG + 16384 + buf*8192
constexpr int SMEM_BYTES = HG0 + 2 * 32768;     // 182272
}

__device__ float g_Wf[64 * 256];
__device__ float g_b2p[256];

__device__ __forceinline__ uint32_t s2u(const void* p) {
    uint32_t a;
    asm("{.reg .u64 t; cvta.to.shared.u64 t,%1; cvt.u32.u64 %0,t;}" : "=r"(a) : "l"(p));
    return a;
}
__device__ __forceinline__ void ldsm4(uint32_t a, uint32_t* r) {
    asm volatile("ldmatrix.sync.aligned.m8n8.x4.shared.b16 {%0,%1,%2,%3},[%4];"
        : "=r"(r[0]), "=r"(r[1]), "=r"(r[2]), "=r"(r[3]) : "r"(a));
}
__device__ __forceinline__ void mmah(float* d, const uint32_t* a, uint32_t b0, uint32_t b1) {
    asm volatile("mma.sync.aligned.m16n8k16.row.col.f32.f16.f16.f32 "
        "{%0,%1,%2,%3},{%4,%5,%6,%7},{%8,%9},{%0,%1,%2,%3};"
        : "+f"(d[0]), "+f"(d[1]), "+f"(d[2]), "+f"(d[3])
        : "r"(a[0]), "r"(a[1]), "r"(a[2]), "r"(a[3]), "r"(b0), "r"(b1));
}
__device__ __forceinline__ float tapx(float x) {
    float r;
    asm("tanh.approx.f32 %0,%1;" : "=f"(r) : "f"(x));
    return r;
}
__device__ __forceinline__ float sigm(float x) { return fmaf(tapx(0.5f * x), 0.5f, 0.5f); }
__device__ __forceinline__ uint32_t pkh(float a, float b) {
    __half2 t = __floats2half2_rn(a, b);
    return *reinterpret_cast<uint32_t*>(&t);
}
__device__ __forceinline__ int sw8(int r) { return (r + (r >> 3)) & 7; }
// 128-thread barrier per (group, m-half): ids 1..4 ; 256-thread per group: ids 5..6
#define BAR_HALF(id) asm volatile("bar.sync %0, 128;" :: "r"(id) : "memory")
#define BAR_GRP(id)  asm volatile("bar.sync %0, 256;" :: "r"(id) : "memory")

__global__ void prep_kernel(const float* __restrict__ Wd, const float* __restrict__ bd,
                            const float* __restrict__ W2, const float* __restrict__ b2) {
    const int n = threadIdx.x;
    float s2 = b2[n];
    for (int j = 0; j < 30; ++j) s2 += bd[j] * W2[j * 256 + n];
    g_b2p[n] = s2;
    for (int k = 0; k < 64; ++k) {
        float s = 0.f;
        for (int j = 0; j < 30; ++j) s += Wd[k * 30 + j] * W2[j * 256 + n];
        g_Wf[k * 256 + n] = s;
    }
}

__global__ void __launch_bounds__(THREADS, 1)
rnn_mma_kernel(const float* __restrict__ x, const float* __restrict__ W1,
               const float* __restrict__ U1, const float* __restrict__ b1,
               const float* __restrict__ U2, const float* __restrict__ Wf,
               const float* __restrict__ bf, float* __restrict__ out)
{
    extern __shared__ char sm[];
    const uint32_t sb = s2u(sm);
    const int tid = threadIdx.x, wid = tid >> 5, lid = tid & 31;
    const int g = wid >> 3;            // tile group (0/1)
    const int w8 = wid & 7;            // warp within group
    const int mt = w8 >> 2, nq = w8 & 3;   // SMSP = wid&3 hosts warps of both groups
    const int grp = lid >> 2, tig = lid & 3;
    const int HG = HG0 + g * 32768;    // this group's h area
    const int barH = 1 + g * 2 + mt, barG = 5 + g;

    auto ocol = [](int p) { return (((p >> 4) & 3) << 6) + ((p >> 6) << 4) + (p & 15); };

    // ---- stage shared weights once (fp16 single) ----
    auto stageH = [&](const float* src, int off) {
        for (int idx = tid; idx < 2048; idx += THREADS) {
            const int p = idx >> 3, kc = idx & 7;
            const float* s0 = src + ocol(p);
            uint32_t v[4];
#pragma unroll
            for (int i = 0; i < 4; ++i)
                v[i] = pkh(s0[(kc * 8 + 2 * i) * 256], s0[(kc * 8 + 2 * i + 1) * 256]);
            *reinterpret_cast<uint4*>(sm + off + p * 128 + ((kc ^ sw8(p)) << 4)) =
                *reinterpret_cast<uint4*>(v);
        }
    };
    stageH(U1, U1F);
    stageH(g_Wf, FF);
    stageH(U2, U2F);
    for (int idx = tid; idx < 512; idx += THREADS) {   // W1 fp16 [256][32k], data in k0-15
        const int p = idx >> 1, c = idx & 1, oc = ocol(p);
        uint32_t v[4];
#pragma unroll
        for (int i = 0; i < 4; ++i)
            v[i] = pkh(W1[(c * 8 + 2 * i) * 256 + oc], W1[(c * 8 + 2 * i + 1) * 256 + oc]);
        *reinterpret_cast<uint4*>(sm + W1T + p * 64 + ((c ^ (p & 3)) << 4)) =
            *reinterpret_cast<uint4*>(v);
    }
    if (tid < 256) {   // biases interleaved: bi[u*4+gate] = b[gate*64+u]
        float* b1i = reinterpret_cast<float*>(sm + BIAS1);
        float* b2i = reinterpret_cast<float*>(sm + BIAS2);
        const int u = tid >> 2, gg = tid & 3;
        b1i[tid] = b1[gg * 64 + u];
        b2i[tid] = g_b2p[gg * 64 + u];
    }
    __syncthreads();   // the only full-CTA barrier

    const float* bi1 = reinterpret_cast<const float*>(sm + BIAS1);
    const float* bi2 = reinterpret_cast<const float*>(sm + BIAS2);

    auto bAddr = [&](int base, int jj, int kc) -> uint32_t {
        const int n = nq * 64 + jj * 16 + (lid & 15);
        const int c = kc * 2 + (lid >> 4);
        return sb + base + n * 128 + ((c ^ sw8(n)) << 4);
    };
    auto aAddr = [&](int base, int mf, int kc) -> uint32_t {
        const int r = mt * 32 + mf * 16 + (lid & 15);
        const int c = kc * 2 + (lid >> 4);
        return sb + base + r * 128 + ((c ^ sw8(r)) << 4);
    };
    auto wAddr = [&](int jj) -> uint32_t {
        const int n = nq * 64 + jj * 16 + (lid & 15);
        const int c = lid >> 4;
        return sb + W1T + n * 64 + ((c ^ (n & 3)) << 4);
    };
    // fp16 single-term chunk: acc += A*B
    auto rec1 = [&](float (*acc)[8][4], int aBase, int bBase, int kc) {
        uint32_t ah[2][4], bh[16];
        ldsm4(aAddr(aBase, 0, kc), ah[0]); ldsm4(aAddr(aBase, 1, kc), ah[1]);
#pragma unroll
        for (int jj = 0; jj < 4; ++jj) ldsm4(bAddr(bBase, jj, kc), bh + 4 * jj);
#pragma unroll
        for (int m = 0; m < 2; ++m)
#pragma unroll
            for (int jj = 0; jj < 4; ++jj) {
                mmah(acc[m][2 * jj], ah[m], bh[4 * jj], bh[4 * jj + 2]);
                mmah(acc[m][2 * jj + 1], ah[m], bh[4 * jj + 1], bh[4 * jj + 3]);
            }
    };
    // acc init straight from smem bias (saves 32 registers vs register arrays)
    auto initAcc = [&](float (*acc)[8][4], const float* bi) {
#pragma unroll
        for (int j2 = 0; j2 < 2; ++j2)
#pragma unroll
            for (int e = 0; e < 2; ++e) {
                const int u = nq * 16 + j2 * 8 + tig * 2 + e;
                const float4 bv = *reinterpret_cast<const float4*>(bi + u * 4);
                const float bva[4] = {bv.x, bv.y, bv.z, bv.w};
#pragma unroll
                for (int m = 0; m < 2; ++m)
#pragma unroll
                    for (int gg = 0; gg < 4; ++gg) {
                        acc[m][gg * 2 + j2][e]     = bva[gg];
                        acc[m][gg * 2 + j2][2 + e] = bva[gg];
                    }
            }
    };
    // epilogue: LSTM gates (bias pre-added) -> packed fp16 h stores (optional)
    auto epi = [&](float (*acc)[8][4], float (*cst)[8], int hBase, bool storeH,
                   bool relu, bool head, float (*pout)[2][4]) {
#pragma unroll
        for (int m = 0; m < 2; ++m)
#pragma unroll
            for (int j2 = 0; j2 < 2; ++j2)
#pragma unroll
                for (int p = 0; p < 2; ++p) {
                    float hv[2];
#pragma unroll
                    for (int e = 0; e < 2; ++e) {
                        const int r = 2 * p + e;
                        const float iv = sigm(acc[m][j2][r]);
                        const float fv = sigm(acc[m][2 + j2][r]);
                        const float gv = relu ? fmaxf(acc[m][4 + j2][r], 0.f)
                                              : tapx(acc[m][4 + j2][r]);
                        const float ov = sigm(acc[m][6 + j2][r]);
                        const int ci = j2 * 4 + r;
                        const float cc = fmaf(fv, cst[m][ci], iv * gv);
                        cst[m][ci] = cc;
                        hv[e] = ov * (relu ? fmaxf(cc, 0.f) : tapx(cc));
                        if (head) {
                            const int u = nq * 16 + j2 * 8 + tig * 2 + e;
                            const float4 w = *reinterpret_cast<const float4*>(Wf + u * 4);
                            float* po = pout[m][p];
                            po[0] = fmaf(hv[e], w.x, po[0]);
                            po[1] = fmaf(hv[e], w.y, po[1]);
                            po[2] = fmaf(hv[e], w.z, po[2]);
                            po[3] = fmaf(hv[e], w.w, po[3]);
                        }
                    }
                    if (storeH) {
                        const int u0 = nq * 16 + j2 * 8 + tig * 2;
                        const int s = mt * 32 + m * 16 + grp + p * 8;
                        const int ad = s * 128 + (((u0 >> 3) ^ sw8(s)) << 4) + (u0 & 7) * 2;
                        *reinterpret_cast<uint32_t*>(sm + hBase + ad) = pkh(hv[0], hv[1]);
                    }
                }
    };

    // ---- persistent tile loop: each group strides independently ----
    for (int tile = blockIdx.x * 2 + g; tile < NTILES; tile += gridDim.x * 2) {
        float c1[2][8], c2[2][8], pout[2][2][4];
#pragma unroll
        for (int m = 0; m < 2; ++m)
#pragma unroll
            for (int i = 0; i < 8; ++i) { c1[m][i] = 0.f; c2[m][i] = 0.f; }
#pragma unroll
        for (int m = 0; m < 2; ++m)
#pragma unroll
            for (int h = 0; h < 2; ++h)
#pragma unroll
                for (int i = 0; i < 4; ++i) pout[m][h][i] = 0.f;
        const float* xb = x + (size_t)(tile * 64 + mt * 32 + grp) * (TT * 16) + tig * 2;

        for (int t = 0; t < TT; ++t) {
            const int cb = (t & 1) * 8192, pb = ((t & 1) ^ 1) * 8192;
            float2 v[2][4];
#pragma unroll
            for (int m = 0; m < 2; ++m) {
                const float* px = xb + (size_t)m * 16 * (TT * 16) + t * 16;
                v[m][0] = *reinterpret_cast<const float2*>(px);
                v[m][1] = *reinterpret_cast<const float2*>(px + 8 * TT * 16);
                v[m][2] = *reinterpret_cast<const float2*>(px + 8);
                v[m][3] = *reinterpret_cast<const float2*>(px + 8 * TT * 16 + 8);
            }

            // ---- z1 = b1 + h1@U1 + x@W1 (single-term fp16) ----
            float acc[2][8][4];
            initAcc(acc, bi1);
            if (t)
#pragma unroll
                for (int kc = 0; kc < 4; ++kc) rec1(acc, HG + pb, U1F, kc);
            {
                uint32_t axh[2][4];
#pragma unroll
                for (int m = 0; m < 2; ++m)
#pragma unroll
                    for (int i = 0; i < 4; ++i)
                        axh[m][i] = pkh(v[m][i].x, v[m][i].y);
                uint32_t bh[16];
#pragma unroll
                for (int jj = 0; jj < 4; ++jj) ldsm4(wAddr(jj), bh + 4 * jj);
#pragma unroll
                for (int m = 0; m < 2; ++m)
#pragma unroll
                    for (int jj = 0; jj < 4; ++jj) {
                        mmah(acc[m][2 * jj], axh[m], bh[4 * jj], bh[4 * jj + 2]);
                        mmah(acc[m][2 * jj + 1], axh[m], bh[4 * jj + 1], bh[4 * jj + 3]);
                    }
            }
            epi(acc, c1, HG + cb, true, false, false, nullptr);
            BAR_HALF(barH);   // 4 warps of this group-half sync

            // ---- z2 = b2' + h1@Wfused + h2@U2 (single-term fp16) ----
            float acc2[2][8][4];
            initAcc(acc2, bi2);
#pragma unroll
            for (int kc = 0; kc < 4; ++kc) rec1(acc2, HG + cb, FF, kc);
            if (t)
#pragma unroll
                for (int kc = 0; kc < 4; ++kc) rec1(acc2, HG + 16384 + pb, U2F, kc);
            epi(acc2, c2, HG + 16384 + cb, t < TT - 1, true, t == TT - 1, pout);
            // no barrier: BAR_HALF(t+1) orders epi2 before any conflicting access
        }

        // ---- head: shfl-reduce over tig, smem-reduce over nq (group-local) ----
#pragma unroll
        for (int m = 0; m < 2; ++m)
#pragma unroll
            for (int h = 0; h < 2; ++h)
#pragma unroll
                for (int o = 0; o < 4; ++o) {
                    pout[m][h][o] += __shfl_xor_sync(0xffffffffu, pout[m][h][o], 1);
                    pout[m][h][o] += __shfl_xor_sync(0xffffffffu, pout[m][h][o], 2);
                }
        BAR_GRP(barG);   // group re-converge: scr aliases this group's h1 buf0
        float* scr = reinterpret_cast<float*>(sm + HG);   // h1 buf0 dead (last cb = buf1)
        if (tig == 0)
#pragma unroll
            for (int m = 0; m < 2; ++m)
#pragma unroll
                for (int h = 0; h < 2; ++h) {
                    const int s0 = mt * 32 + m * 16 + grp + h * 8;
                    *reinterpret_cast<float4*>(scr + (s0 * 4 + nq) * 4) =
                        make_float4(pout[m][h][0], pout[m][h][1], pout[m][h][2], pout[m][h][3]);
                }
        BAR_GRP(barG);
        {
            const int lt = tid & 255;
            const int s = lt >> 2, o = lt & 3;
            const float vv = scr[(s * 4 + 0) * 4 + o] + scr[(s * 4 + 1) * 4 + o] +
                             scr[(s * 4 + 2) * 4 + o] + scr[(s * 4 + 3) * 4 + o] + bf[o];
            out[(size_t)tile * 256 + s * 4 + o] = vv;
        }
        BAR_GRP(barG);   // scr reads done before next tile's epi1 writes h1
    }
}

extern "C" void kernel_launch(void* const* d_in, const int* in_sizes, int n_in,
                              void* d_out, int out_size) {
    (void)in_sizes; (void)n_in; (void)out_size;
    const float* x  = (const float*)d_in[0];
    const float* W1 = (const float*)d_in[1];
    const float* U1 = (const float*)d_in[2];
    const float* b1 = (const float*)d_in[3];
    const float* Wd = (const float*)d_in[4];
    const float* bd = (const float*)d_in[5];
    const float* W2 = (const float*)d_in[6];
    const float* U2 = (const float*)d_in[7];
    const float* b2 = (const float*)d_in[8];
    const float* Wf = (const float*)d_in[9];
    const float* bf = (const float*)d_in[10];
    float* out = (float*)d_out;

    prep_kernel<<<1, 256>>>(Wd, bd, W2, b2);
    cudaFuncSetAttribute(rnn_mma_kernel, cudaFuncAttributeMaxDynamicSharedMemorySize, SMEM_BYTES);
    rnn_mma_kernel<<<GRID, THREADS, SMEM_BYTES>>>(x, W1, U1, b1, U2, Wf, bf, out);
}